// round 1
// baseline (speedup 1.0000x reference)
#include <cuda_runtime.h>

#define NPTS 2000000
#define NG   16384

typedef unsigned long long u64;

// Scratch (device globals: allocation-free, graph-capturable)
__device__ float g_xe[NPTS * 5];      // 40 MB: per-point embedding
__device__ float g_aggr[NG * 5];      // segment sum of xe
__device__ float g_glob[NG * 4];      // global features (padded-friendly: 4 = float4)
__device__ float g_pooled[NG * 32];   // segment sum of xo

// ---------- packed f32x2 helpers (Blackwell FFMA2: 2x FFMA throughput) ----------
__device__ __forceinline__ u64 pk2(float lo, float hi) {
    u64 r; asm("mov.b64 %0, {%1, %2};" : "=l"(r) : "f"(lo), "f"(hi)); return r;
}
__device__ __forceinline__ void up2(u64 v, float& lo, float& hi) {
    asm("mov.b64 {%0, %1}, %2;" : "=f"(lo), "=f"(hi) : "l"(v));
}
__device__ __forceinline__ u64 ffma2(u64 a, u64 b, u64 c) {
    u64 d; asm("fma.rn.f32x2 %0, %1, %2, %3;" : "=l"(d) : "l"(a), "l"(b), "l"(c)); return d;
}
// leaky_relu(x, 0.01) == max(x, 0.01x) exactly (slope in (0,1))
__device__ __forceinline__ float lrelu(float v) { return fmaxf(v, 0.01f * v); }

// ---------- zero the accumulators (graph replays re-run this) ----------
__global__ void __launch_bounds__(256) k_zero() {
    int i = blockIdx.x * 256 + threadIdx.x;
    float4 z = make_float4(0.f, 0.f, 0.f, 0.f);
    if (i < NG * 5 / 4)  ((float4*)g_aggr)[i]   = z;
    if (i < NG * 32 / 4) ((float4*)g_pooled)[i] = z;
}

// ---------- warp segmented-sum helper pieces are inlined at call sites ----------

// Pass 1: xe = ffn(x, We1[3x40], We2[40x5]); store xe; segment-sum -> g_aggr
__global__ void __launch_bounds__(256) k_emb(const float* __restrict__ x,
                                             const int* __restrict__ batch,
                                             const float* __restrict__ We1,
                                             const float* __restrict__ We2) {
    __shared__ __align__(16) float sW1[120];   // [3][40]
    __shared__ __align__(16) float sW2t[200];  // transposed: [5][40]
    int tid = threadIdx.x;
    if (tid < 120) sW1[tid] = We1[tid];
    if (tid < 200) { int j = tid / 40, k = tid % 40; sW2t[tid] = We2[k * 5 + j]; }
    __syncthreads();

    int i = blockIdx.x * 256 + tid;
    if (i >= NPTS) return;   // N % 32 == 0 -> whole warps retire together

    float x0 = x[3 * i + 0], x1 = x[3 * i + 1], x2 = x[3 * i + 2];
    u64 a0 = pk2(x0, x0), a1 = pk2(x1, x1), a2 = pk2(x2, x2);
    const u64* w0 = (const u64*)(sW1);
    const u64* w1 = (const u64*)(sW1 + 40);
    const u64* w2 = (const u64*)(sW1 + 80);

    u64 hp[20];
#pragma unroll
    for (int j = 0; j < 20; j++) {
        u64 acc = ffma2(a0, w0[j], 0ULL);
        acc = ffma2(a1, w1[j], acc);
        acc = ffma2(a2, w2[j], acc);
        float lo, hi; up2(acc, lo, hi);
        hp[j] = pk2(lrelu(lo), lrelu(hi));
    }

    float xe[5];
#pragma unroll
    for (int j = 0; j < 5; j++) {
        const u64* wr = (const u64*)(sW2t + j * 40);
        u64 acc = 0ULL;
#pragma unroll
        for (int k = 0; k < 20; k++) acc = ffma2(hp[k], wr[k], acc);
        float lo, hi; up2(acc, lo, hi);
        xe[j] = lrelu(lo + hi);
    }
#pragma unroll
    for (int j = 0; j < 5; j++) g_xe[i * 5 + j] = xe[j];

    // Sorted-batch warp-segmented reduction: only run-leaders do atomics.
    int b = batch[i];
    unsigned peers = __match_any_sync(0xffffffffu, b);  // contiguous run (sorted)
    int lane = tid & 31;
    int hiL = 31 - __clz(peers);
    bool leader = (lane == __ffs(peers) - 1);
#pragma unroll
    for (int c = 0; c < 5; c++) {
        float v = xe[c];
#pragma unroll
        for (int d = 1; d < 32; d <<= 1) {
            float t = __shfl_down_sync(0xffffffffu, v, d);
            if (lane + d <= hiL) v += t;
        }
        if (leader) atomicAdd(&g_aggr[b * 5 + c], v);
    }
}

// Pass 2: x_global = ffn(x_aggr, Wg1[5x40], Wg2[40x4])  (one thread per graph)
__global__ void __launch_bounds__(256) k_glob(const float* __restrict__ Wg1,
                                              const float* __restrict__ Wg2) {
    __shared__ __align__(16) float sW1[200];   // [5][40]
    __shared__ __align__(16) float sW2t[160];  // transposed: [4][40]
    int tid = threadIdx.x;
    if (tid < 200) sW1[tid] = Wg1[tid];
    if (tid < 160) { int j = tid / 40, k = tid % 40; sW2t[tid] = Wg2[k * 4 + j]; }
    __syncthreads();

    int g = blockIdx.x * 256 + tid;   // grid = 64 blocks exactly
    float in5[5];
#pragma unroll
    for (int j = 0; j < 5; j++) in5[j] = g_aggr[g * 5 + j];

    u64 acc[20];
#pragma unroll
    for (int j = 0; j < 20; j++) acc[j] = 0ULL;
#pragma unroll
    for (int k = 0; k < 5; k++) {
        u64 a = pk2(in5[k], in5[k]);
        const u64* wr = (const u64*)(sW1 + k * 40);
#pragma unroll
        for (int j = 0; j < 20; j++) acc[j] = ffma2(a, wr[j], acc[j]);
    }
    u64 hp[20];
#pragma unroll
    for (int j = 0; j < 20; j++) {
        float lo, hi; up2(acc[j], lo, hi);
        hp[j] = pk2(lrelu(lo), lrelu(hi));
    }
    float og[4];
#pragma unroll
    for (int j = 0; j < 4; j++) {
        const u64* wr = (const u64*)(sW2t + j * 40);
        u64 a = 0ULL;
#pragma unroll
        for (int k = 0; k < 20; k++) a = ffma2(hp[k], wr[k], a);
        float lo, hi; up2(a, lo, hi);
        og[j] = lrelu(lo + hi);
    }
    ((float4*)g_glob)[g] = make_float4(og[0], og[1], og[2], og[3]);
}

// Pass 3: xo = ffn([xe, xg[batch]], Wo1[9x40], Wo2[40x32]); segment-sum -> g_pooled
__global__ void __launch_bounds__(256) k_out(const int* __restrict__ batch,
                                             const float* __restrict__ Wo1,
                                             const float* __restrict__ Wo2) {
    __shared__ __align__(16) float sW1[360];    // [9][40]
    __shared__ __align__(16) float sW2[1280];   // [40][32]
    int tid = threadIdx.x;
    for (int t = tid; t < 360; t += 256)  sW1[t] = Wo1[t];
    for (int t = tid; t < 1280; t += 256) sW2[t] = Wo2[t];
    __syncthreads();

    int i = blockIdx.x * 256 + tid;
    if (i >= NPTS) return;

    int b = batch[i];
    float4 xg = ((const float4*)g_glob)[b];
    float in9[9];
#pragma unroll
    for (int j = 0; j < 5; j++) in9[j] = g_xe[i * 5 + j];
    in9[5] = xg.x; in9[6] = xg.y; in9[7] = xg.z; in9[8] = xg.w;

    // hidden: 9 -> 40
    u64 acc[20];
#pragma unroll
    for (int j = 0; j < 20; j++) acc[j] = 0ULL;
#pragma unroll
    for (int k = 0; k < 9; k++) {
        u64 a = pk2(in9[k], in9[k]);
        const u64* wr = (const u64*)(sW1 + k * 40);
#pragma unroll
        for (int j = 0; j < 20; j++) acc[j] = ffma2(a, wr[j], acc[j]);
    }
    float h2[40];
#pragma unroll
    for (int j = 0; j < 20; j++) {
        float lo, hi; up2(acc[j], lo, hi);
        h2[2 * j] = lrelu(lo); h2[2 * j + 1] = lrelu(hi);
    }

    // out: 40 -> 32
    u64 o[16];
#pragma unroll
    for (int j = 0; j < 16; j++) o[j] = 0ULL;
#pragma unroll
    for (int k = 0; k < 40; k++) {
        u64 a = pk2(h2[k], h2[k]);
        const u64* wr = (const u64*)(sW2 + k * 32);
#pragma unroll
        for (int j = 0; j < 16; j++) o[j] = ffma2(a, wr[j], o[j]);
    }
    float xo[32];
#pragma unroll
    for (int j = 0; j < 16; j++) {
        float lo, hi; up2(o[j], lo, hi);
        xo[2 * j] = lrelu(lo); xo[2 * j + 1] = lrelu(hi);
    }

    // warp-segmented sum -> g_pooled
    unsigned peers = __match_any_sync(0xffffffffu, b);
    int lane = tid & 31;
    int hiL = 31 - __clz(peers);
    bool leader = (lane == __ffs(peers) - 1);
#pragma unroll
    for (int c = 0; c < 32; c++) {
        float v = xo[c];
#pragma unroll
        for (int d = 1; d < 32; d <<= 1) {
            float t = __shfl_down_sync(0xffffffffu, v, d);
            if (lane + d <= hiL) v += t;
        }
        if (leader) atomicAdd(&g_pooled[b * 32 + c], v);
    }
}

// Pass 4: out = ffn(pooled, Wd1[32x40], Wd2[40x1], final_linear=True)
__global__ void __launch_bounds__(256) k_disc(const float* __restrict__ Wd1,
                                              const float* __restrict__ Wd2,
                                              float* __restrict__ out) {
    __shared__ __align__(16) float sW1[1280];  // [32][40]
    __shared__ __align__(16) float sW2[40];    // [40]
    int tid = threadIdx.x;
    for (int t = tid; t < 1280; t += 256) sW1[t] = Wd1[t];
    if (tid < 40) sW2[tid] = Wd2[tid];
    __syncthreads();

    int g = blockIdx.x * 256 + tid;   // grid = 64 blocks exactly
    float p[32];
#pragma unroll
    for (int j = 0; j < 32; j++) p[j] = g_pooled[g * 32 + j];

    u64 acc[20];
#pragma unroll
    for (int j = 0; j < 20; j++) acc[j] = 0ULL;
#pragma unroll
    for (int k = 0; k < 32; k++) {
        u64 a = pk2(p[k], p[k]);
        const u64* wr = (const u64*)(sW1 + k * 40);
#pragma unroll
        for (int j = 0; j < 20; j++) acc[j] = ffma2(a, wr[j], acc[j]);
    }
    u64 s = 0ULL;
    const u64* w2 = (const u64*)sW2;
#pragma unroll
    for (int j = 0; j < 20; j++) {
        float lo, hi; up2(acc[j], lo, hi);
        s = ffma2(pk2(lrelu(lo), lrelu(hi)), w2[j], s);
    }
    float lo, hi; up2(s, lo, hi);
    out[g] = lo + hi;   // final_linear: no activation
}

extern "C" void kernel_launch(void* const* d_in, const int* in_sizes, int n_in,
                              void* d_out, int out_size) {
    const float* x    = (const float*)d_in[0];
    const int*   batch = (const int*)d_in[1];   // JAX x64 disabled -> int32
    const float* We1 = (const float*)d_in[2];
    const float* We2 = (const float*)d_in[3];
    const float* Wg1 = (const float*)d_in[4];
    const float* Wg2 = (const float*)d_in[5];
    const float* Wo1 = (const float*)d_in[6];
    const float* Wo2 = (const float*)d_in[7];
    const float* Wd1 = (const float*)d_in[8];
    const float* Wd2 = (const float*)d_in[9];
    float* out = (float*)d_out;

    const int nblk = (NPTS + 255) / 256;
    k_zero<<<512, 256>>>();
    k_emb<<<nblk, 256>>>(x, batch, We1, We2);
    k_glob<<<NG / 256, 256>>>(Wg1, Wg2);
    k_out<<<nblk, 256>>>(batch, Wo1, Wo2);
    k_disc<<<NG / 256, 256>>>(Wd1, Wd2, out);
}

// round 2
// speedup vs baseline: 1.6146x; 1.6146x over previous
#include <cuda_runtime.h>

#define NPTS 2000000
#define NG   16384

typedef unsigned long long u64;

// Scratch (device globals: allocation-free, graph-capturable)
__device__ float g_xe[NPTS * 5];      // 40 MB: per-point embedding
__device__ float g_aggr[NG * 5];      // segment sum of xe
__device__ float g_glob[NG * 4];      // global features
__device__ float g_pooled[NG * 32];   // segment sum of xo

// ---------- packed f32x2 helpers (Blackwell FFMA2) ----------
__device__ __forceinline__ u64 pk2(float lo, float hi) {
    u64 r; asm("mov.b64 %0, {%1, %2};" : "=l"(r) : "f"(lo), "f"(hi)); return r;
}
__device__ __forceinline__ void up2(u64 v, float& lo, float& hi) {
    asm("mov.b64 {%0, %1}, %2;" : "=f"(lo), "=f"(hi) : "l"(v));
}
__device__ __forceinline__ u64 ffma2(u64 a, u64 b, u64 c) {
    u64 d; asm("fma.rn.f32x2 %0, %1, %2, %3;" : "=l"(d) : "l"(a), "l"(b), "l"(c)); return d;
}
__device__ __forceinline__ u64 d2u_lo(double2 w) { return __double_as_longlong(w.x); }
__device__ __forceinline__ u64 d2u_hi(double2 w) { return __double_as_longlong(w.y); }
// leaky_relu(x, 0.01) == max(x, 0.01x) exactly (slope in (0,1))
__device__ __forceinline__ float lrelu(float v) { return fmaxf(v, 0.01f * v); }

// ---------- zero g_aggr (g_pooled is zeroed inside k_glob) ----------
__global__ void __launch_bounds__(256) k_zero() {
    int i = blockIdx.x * 256 + threadIdx.x;
    if (i < NG * 5 / 4) ((float4*)g_aggr)[i] = make_float4(0.f, 0.f, 0.f, 0.f);
}

// =====================================================================
// Pass 1: xe = ffn(x, We1[3x40], We2[40x5]); store xe; segment-sum -> g_aggr
// P=2 points per thread, LDS.128 weight loads.
// =====================================================================
__global__ void __launch_bounds__(256, 2) k_emb(const float* __restrict__ x,
                                                const int* __restrict__ batch,
                                                const float* __restrict__ We1,
                                                const float* __restrict__ We2) {
    __shared__ __align__(16) float sW1[120];   // [3][40]
    __shared__ __align__(16) float sW2t[200];  // transposed: [5][40]
    int tid = threadIdx.x;
    if (tid < 120) sW1[tid] = We1[tid];
    if (tid < 200) { int j = tid / 40, k = tid % 40; sW2t[tid] = We2[k * 5 + j]; }
    __syncthreads();

    int t = blockIdx.x * 256 + tid;
    int i0 = t * 2;
    if (i0 >= NPTS) return;   // NPTS % 64 == 0 -> surviving warps are full

    // x: 6 consecutive floats (two points) at 24-byte offset -> float2 loads (8B aligned)
    const float2* xp = (const float2*)(x + i0 * 3);
    float2 p0 = xp[0], p1 = xp[1], p2 = xp[2];
    float inA[3] = {p0.x, p0.y, p1.x};
    float inB[3] = {p1.y, p2.x, p2.y};

    // hidden 3 -> 40 (packed pairs)
    u64 hA[20], hB[20];
#pragma unroll
    for (int j = 0; j < 20; j++) { hA[j] = 0ULL; hB[j] = 0ULL; }
#pragma unroll
    for (int k = 0; k < 3; k++) {
        u64 aA = pk2(inA[k], inA[k]);
        u64 aB = pk2(inB[k], inB[k]);
        const double2* wr = (const double2*)(sW1 + k * 40);
#pragma unroll
        for (int q = 0; q < 10; q++) {
            double2 w = wr[q];
            u64 w0 = d2u_lo(w), w1 = d2u_hi(w);
            hA[2 * q]     = ffma2(aA, w0, hA[2 * q]);
            hA[2 * q + 1] = ffma2(aA, w1, hA[2 * q + 1]);
            hB[2 * q]     = ffma2(aB, w0, hB[2 * q]);
            hB[2 * q + 1] = ffma2(aB, w1, hB[2 * q + 1]);
        }
    }
#pragma unroll
    for (int j = 0; j < 20; j++) {
        float lo, hi;
        up2(hA[j], lo, hi); hA[j] = pk2(lrelu(lo), lrelu(hi));
        up2(hB[j], lo, hi); hB[j] = pk2(lrelu(lo), lrelu(hi));
    }

    // out 40 -> 5 (dot products against transposed W2 rows)
    float xeA[5], xeB[5];
#pragma unroll
    for (int j = 0; j < 5; j++) {
        const double2* wr = (const double2*)(sW2t + j * 40);
        u64 aA = 0ULL, aB = 0ULL;
#pragma unroll
        for (int q = 0; q < 10; q++) {
            double2 w = wr[q];
            u64 w0 = d2u_lo(w), w1 = d2u_hi(w);
            aA = ffma2(hA[2 * q], w0, aA); aA = ffma2(hA[2 * q + 1], w1, aA);
            aB = ffma2(hB[2 * q], w0, aB); aB = ffma2(hB[2 * q + 1], w1, aB);
        }
        float lo, hi;
        up2(aA, lo, hi); xeA[j] = lrelu(lo + hi);
        up2(aB, lo, hi); xeB[j] = lrelu(lo + hi);
    }

    // store xe for both points: 10 consecutive floats, 8B-aligned -> 5 STG.64
    {
        float2* xo = (float2*)(g_xe + i0 * 5);
        xo[0] = make_float2(xeA[0], xeA[1]);
        xo[1] = make_float2(xeA[2], xeA[3]);
        xo[2] = make_float2(xeA[4], xeB[0]);
        xo[3] = make_float2(xeB[1], xeB[2]);
        xo[4] = make_float2(xeB[3], xeB[4]);
    }

    // segmented sum -> g_aggr
    int2 bb = *(const int2*)(batch + i0);
    int bA = bb.x, bB = bb.y;
    bool same = (bA == bB);
    unsigned peers = __match_any_sync(0xffffffffu, bA);
    int lane = tid & 31;
    int hiL = 31 - __clz(peers);
    bool leader = (lane == __ffs(peers) - 1);
#pragma unroll
    for (int c = 0; c < 5; c++) {
        float v = same ? (xeA[c] + xeB[c]) : xeA[c];
#pragma unroll
        for (int d = 1; d < 32; d <<= 1) {
            float s = __shfl_down_sync(0xffffffffu, v, d);
            if (lane + d <= hiL) v += s;
        }
        if (leader) atomicAdd(&g_aggr[bA * 5 + c], v);
        if (!same)  atomicAdd(&g_aggr[bB * 5 + c], xeB[c]);  // rare boundary leftover
    }
}

// =====================================================================
// Pass 2: x_global = ffn(x_aggr, Wg1[5x40], Wg2[40x4]); also zero g_pooled
// =====================================================================
__global__ void __launch_bounds__(256) k_glob(const float* __restrict__ Wg1,
                                              const float* __restrict__ Wg2) {
    __shared__ __align__(16) float sW1[200];   // [5][40]
    __shared__ __align__(16) float sW2t[160];  // transposed: [4][40]
    int tid = threadIdx.x;
    if (tid < 200) sW1[tid] = Wg1[tid];
    if (tid < 160) { int j = tid / 40, k = tid % 40; sW2t[tid] = Wg2[k * 4 + j]; }
    __syncthreads();

    int g = blockIdx.x * 256 + tid;   // grid = NG/256 = 64 blocks exactly

    // zero g_pooled: 128K float4 over 16384 threads -> 8 each
    {
        float4 z = make_float4(0.f, 0.f, 0.f, 0.f);
        float4* pp = (float4*)g_pooled;
#pragma unroll
        for (int r = 0; r < 8; r++) pp[g * 8 + r] = z;
    }

    float in5[5];
#pragma unroll
    for (int j = 0; j < 5; j++) in5[j] = g_aggr[g * 5 + j];

    u64 acc[20];
#pragma unroll
    for (int j = 0; j < 20; j++) acc[j] = 0ULL;
#pragma unroll
    for (int k = 0; k < 5; k++) {
        u64 a = pk2(in5[k], in5[k]);
        const double2* wr = (const double2*)(sW1 + k * 40);
#pragma unroll
        for (int q = 0; q < 10; q++) {
            double2 w = wr[q];
            acc[2 * q]     = ffma2(a, d2u_lo(w), acc[2 * q]);
            acc[2 * q + 1] = ffma2(a, d2u_hi(w), acc[2 * q + 1]);
        }
    }
#pragma unroll
    for (int j = 0; j < 20; j++) {
        float lo, hi; up2(acc[j], lo, hi);
        acc[j] = pk2(lrelu(lo), lrelu(hi));
    }
    float og[4];
#pragma unroll
    for (int j = 0; j < 4; j++) {
        const double2* wr = (const double2*)(sW2t + j * 40);
        u64 a = 0ULL;
#pragma unroll
        for (int q = 0; q < 10; q++) {
            double2 w = wr[q];
            a = ffma2(acc[2 * q], d2u_lo(w), a);
            a = ffma2(acc[2 * q + 1], d2u_hi(w), a);
        }
        float lo, hi; up2(a, lo, hi);
        og[j] = lrelu(lo + hi);
    }
    ((float4*)g_glob)[g] = make_float4(og[0], og[1], og[2], og[3]);
}

// =====================================================================
// Pass 3: xo = ffn([xe, xg[batch]], Wo1[9x40], Wo2[40x32]); segment-sum -> g_pooled
// P=2 points/thread; layer2 computed in two 16-output halves to cap registers.
// =====================================================================
__global__ void __launch_bounds__(256, 2) k_out(const int* __restrict__ batch,
                                                const float* __restrict__ Wo1,
                                                const float* __restrict__ Wo2) {
    __shared__ __align__(16) float sW1[360];    // [9][40]
    __shared__ __align__(16) float sW2[1280];   // [40][32]
    int tid = threadIdx.x;
    for (int t = tid; t < 360; t += 256)  sW1[t] = Wo1[t];
    for (int t = tid; t < 1280; t += 256) sW2[t] = Wo2[t];
    __syncthreads();

    int t = blockIdx.x * 256 + tid;
    int i0 = t * 2;
    if (i0 >= NPTS) return;   // NPTS % 64 == 0 -> surviving warps are full

    int2 bb = *(const int2*)(batch + i0);
    int bA = bb.x, bB = bb.y;
    float4 xgA = ((const float4*)g_glob)[bA];
    float4 xgB = ((const float4*)g_glob)[bB];

    float inA[9], inB[9];
    {
        const float2* xep = (const float2*)(g_xe + i0 * 5);
        float2 e0 = xep[0], e1 = xep[1], e2 = xep[2], e3 = xep[3], e4 = xep[4];
        inA[0] = e0.x; inA[1] = e0.y; inA[2] = e1.x; inA[3] = e1.y; inA[4] = e2.x;
        inB[0] = e2.y; inB[1] = e3.x; inB[2] = e3.y; inB[3] = e4.x; inB[4] = e4.y;
        inA[5] = xgA.x; inA[6] = xgA.y; inA[7] = xgA.z; inA[8] = xgA.w;
        inB[5] = xgB.x; inB[6] = xgB.y; inB[7] = xgB.z; inB[8] = xgB.w;
    }

    // hidden 9 -> 40
    u64 hA[20], hB[20];
#pragma unroll
    for (int j = 0; j < 20; j++) { hA[j] = 0ULL; hB[j] = 0ULL; }
#pragma unroll
    for (int k = 0; k < 9; k++) {
        u64 aA = pk2(inA[k], inA[k]);
        u64 aB = pk2(inB[k], inB[k]);
        const double2* wr = (const double2*)(sW1 + k * 40);
#pragma unroll
        for (int q = 0; q < 10; q++) {
            double2 w = wr[q];
            u64 w0 = d2u_lo(w), w1 = d2u_hi(w);
            hA[2 * q]     = ffma2(aA, w0, hA[2 * q]);
            hA[2 * q + 1] = ffma2(aA, w1, hA[2 * q + 1]);
            hB[2 * q]     = ffma2(aB, w0, hB[2 * q]);
            hB[2 * q + 1] = ffma2(aB, w1, hB[2 * q + 1]);
        }
    }
#pragma unroll
    for (int j = 0; j < 20; j++) {
        float lo, hi;
        up2(hA[j], lo, hi); hA[j] = pk2(lrelu(lo), lrelu(hi));
        up2(hB[j], lo, hi); hB[j] = pk2(lrelu(lo), lrelu(hi));
    }

    // segment bookkeeping (computed once)
    bool same = (bA == bB);
    unsigned peers = __match_any_sync(0xffffffffu, bA);
    int lane = tid & 31;
    int hiL = 31 - __clz(peers);
    bool leader = (lane == __ffs(peers) - 1);

    // out 40 -> 32, two halves of 16 outputs; reduce + atomics per half
#pragma unroll
    for (int hf = 0; hf < 2; hf++) {
        u64 oA[8], oB[8];
#pragma unroll
        for (int q = 0; q < 8; q++) { oA[q] = 0ULL; oB[q] = 0ULL; }
#pragma unroll
        for (int j = 0; j < 20; j++) {
            float a0, a1, b0, b1;
            up2(hA[j], a0, a1);
            up2(hB[j], b0, b1);
            {   // k = 2j
                u64 aA = pk2(a0, a0), aB = pk2(b0, b0);
                const double2* wr = (const double2*)(sW2 + (2 * j) * 32 + hf * 16);
#pragma unroll
                for (int q = 0; q < 4; q++) {
                    double2 w = wr[q];
                    u64 w0 = d2u_lo(w), w1 = d2u_hi(w);
                    oA[2 * q]     = ffma2(aA, w0, oA[2 * q]);
                    oA[2 * q + 1] = ffma2(aA, w1, oA[2 * q + 1]);
                    oB[2 * q]     = ffma2(aB, w0, oB[2 * q]);
                    oB[2 * q + 1] = ffma2(aB, w1, oB[2 * q + 1]);
                }
            }
            {   // k = 2j+1
                u64 aA = pk2(a1, a1), aB = pk2(b1, b1);
                const double2* wr = (const double2*)(sW2 + (2 * j + 1) * 32 + hf * 16);
#pragma unroll
                for (int q = 0; q < 4; q++) {
                    double2 w = wr[q];
                    u64 w0 = d2u_lo(w), w1 = d2u_hi(w);
                    oA[2 * q]     = ffma2(aA, w0, oA[2 * q]);
                    oA[2 * q + 1] = ffma2(aA, w1, oA[2 * q + 1]);
                    oB[2 * q]     = ffma2(aB, w0, oB[2 * q]);
                    oB[2 * q + 1] = ffma2(aB, w1, oB[2 * q + 1]);
                }
            }
        }
        // activation + pair-merge + warp segmented reduce + atomics
#pragma unroll
        for (int q = 0; q < 8; q++) {
            float lo, hi;
            up2(oA[q], lo, hi);
            float vA0 = lrelu(lo), vA1 = lrelu(hi);
            up2(oB[q], lo, hi);
            float vB0 = lrelu(lo), vB1 = lrelu(hi);
            int c = hf * 16 + 2 * q;
            float w0 = same ? (vA0 + vB0) : vA0;
            float w1 = same ? (vA1 + vB1) : vA1;
#pragma unroll
            for (int d = 1; d < 32; d <<= 1) {
                float s0 = __shfl_down_sync(0xffffffffu, w0, d);
                float s1 = __shfl_down_sync(0xffffffffu, w1, d);
                if (lane + d <= hiL) { w0 += s0; w1 += s1; }
            }
            if (leader) {
                atomicAdd(&g_pooled[bA * 32 + c],     w0);
                atomicAdd(&g_pooled[bA * 32 + c + 1], w1);
            }
            if (!same) {
                atomicAdd(&g_pooled[bB * 32 + c],     vB0);
                atomicAdd(&g_pooled[bB * 32 + c + 1], vB1);
            }
        }
    }
}

// =====================================================================
// Pass 4: out = ffn(pooled, Wd1[32x40], Wd2[40x1], final_linear=True)
// =====================================================================
__global__ void __launch_bounds__(256) k_disc(const float* __restrict__ Wd1,
                                              const float* __restrict__ Wd2,
                                              float* __restrict__ out) {
    __shared__ __align__(16) float sW1[1280];  // [32][40]
    __shared__ __align__(16) float sW2[40];
    int tid = threadIdx.x;
    for (int t = tid; t < 1280; t += 256) sW1[t] = Wd1[t];
    if (tid < 40) sW2[tid] = Wd2[tid];
    __syncthreads();

    int g = blockIdx.x * 256 + tid;   // grid = NG/256 = 64 blocks exactly
    float p[32];
#pragma unroll
    for (int j = 0; j < 32; j++) p[j] = g_pooled[g * 32 + j];

    u64 acc[20];
#pragma unroll
    for (int j = 0; j < 20; j++) acc[j] = 0ULL;
#pragma unroll
    for (int k = 0; k < 32; k++) {
        u64 a = pk2(p[k], p[k]);
        const double2* wr = (const double2*)(sW1 + k * 40);
#pragma unroll
        for (int q = 0; q < 10; q++) {
            double2 w = wr[q];
            acc[2 * q]     = ffma2(a, d2u_lo(w), acc[2 * q]);
            acc[2 * q + 1] = ffma2(a, d2u_hi(w), acc[2 * q + 1]);
        }
    }
    u64 s = 0ULL;
    const u64* w2 = (const u64*)sW2;
#pragma unroll
    for (int j = 0; j < 20; j++) {
        float lo, hi; up2(acc[j], lo, hi);
        s = ffma2(pk2(lrelu(lo), lrelu(hi)), w2[j], s);
    }
    float lo, hi; up2(s, lo, hi);
    out[g] = lo + hi;   // final_linear: no activation
}

extern "C" void kernel_launch(void* const* d_in, const int* in_sizes, int n_in,
                              void* d_out, int out_size) {
    const float* x     = (const float*)d_in[0];
    const int*   batch = (const int*)d_in[1];
    const float* We1 = (const float*)d_in[2];
    const float* We2 = (const float*)d_in[3];
    const float* Wg1 = (const float*)d_in[4];
    const float* Wg2 = (const float*)d_in[5];
    const float* Wo1 = (const float*)d_in[6];
    const float* Wo2 = (const float*)d_in[7];
    const float* Wd1 = (const float*)d_in[8];
    const float* Wd2 = (const float*)d_in[9];
    float* out = (float*)d_out;

    const int nblk2 = (NPTS / 2 + 255) / 256;   // P=2 kernels
    k_zero<<<(NG * 5 / 4 + 255) / 256, 256>>>();
    k_emb<<<nblk2, 256>>>(x, batch, We1, We2);
    k_glob<<<NG / 256, 256>>>(Wg1, Wg2);
    k_out<<<nblk2, 256>>>(batch, Wo1, Wo2);
    k_disc<<<NG / 256, 256>>>(Wd1, Wd2, out);
}

// round 3
// speedup vs baseline: 1.6532x; 1.0239x over previous
#include <cuda_runtime.h>

#define NPTS 2000000
#define NG   16384

typedef unsigned long long u64;

// Scratch (device globals: allocation-free, graph-capturable)
__device__ float g_xe[NPTS * 5];      // per-point embedding
__device__ float g_aggr[NG * 5];      // segment sum of xe
__device__ float g_glob[NG * 4];      // global features
__device__ float g_pooled[NG * 32];   // segment sum of xo

// Weights in constant memory (uniform-const port: LDCU, off the L1 path).
// Stored as u64 = packed f32 pairs; byte layout identical to the row-major inputs.
__constant__ u64 cWe1[60];    // [3][40]
__constant__ u64 cWe2[100];   // [40][5]
__constant__ u64 cWg1[100];   // [5][40]
__constant__ u64 cWg2[80];    // [40][4]
__constant__ u64 cWo1[180];   // [9][40]
__constant__ u64 cWo2[640];   // [40][32]
__constant__ u64 cWd1[640];   // [32][40]
__constant__ u64 cWd2[20];    // [40][1]

// ---------- packed f32x2 helpers (Blackwell FFMA2) ----------
__device__ __forceinline__ u64 pk2(float lo, float hi) {
    u64 r; asm("mov.b64 %0, {%1, %2};" : "=l"(r) : "f"(lo), "f"(hi)); return r;
}
__device__ __forceinline__ void up2(u64 v, float& lo, float& hi) {
    asm("mov.b64 {%0, %1}, %2;" : "=f"(lo), "=f"(hi) : "l"(v));
}
__device__ __forceinline__ u64 ffma2(u64 a, u64 b, u64 c) {
    u64 d; asm("fma.rn.f32x2 %0, %1, %2, %3;" : "=l"(d) : "l"(a), "l"(b), "l"(c)); return d;
}
// leaky_relu(x, 0.01) == max(x, 0.01x) exactly (slope in (0,1))
__device__ __forceinline__ float lrelu(float v) { return fmaxf(v, 0.01f * v); }

// ---------- zero g_aggr (g_pooled is zeroed inside k_glob) ----------
__global__ void __launch_bounds__(256) k_zero() {
    int i = blockIdx.x * 256 + threadIdx.x;
    if (i < NG * 5 / 4) ((float4*)g_aggr)[i] = make_float4(0.f, 0.f, 0.f, 0.f);
}

// =====================================================================
// Pass 1: xe = ffn(x, We1[3x40], We2[40x5]); store xe; segment-sum -> g_aggr
// =====================================================================
__global__ void __launch_bounds__(256, 2) k_emb(const float* __restrict__ x,
                                                const int* __restrict__ batch) {
    int tid = threadIdx.x;
    int t = blockIdx.x * 256 + tid;
    int i0 = t * 2;
    if (i0 >= NPTS) return;   // NPTS % 64 == 0 -> surviving warps are full

    const float2* xp = (const float2*)(x + i0 * 3);
    float2 p0 = xp[0], p1 = xp[1], p2 = xp[2];
    float inA[3] = {p0.x, p0.y, p1.x};
    float inB[3] = {p1.y, p2.x, p2.y};

    // hidden 3 -> 40 (packed pairs)
    u64 hA[20], hB[20];
#pragma unroll
    for (int j = 0; j < 20; j++) { hA[j] = 0ULL; hB[j] = 0ULL; }
#pragma unroll
    for (int k = 0; k < 3; k++) {
        u64 aA = pk2(inA[k], inA[k]);
        u64 aB = pk2(inB[k], inB[k]);
#pragma unroll
        for (int q = 0; q < 20; q++) {
            u64 w = cWe1[k * 20 + q];
            hA[q] = ffma2(aA, w, hA[q]);
            hB[q] = ffma2(aB, w, hB[q]);
        }
    }
    float hAf[40], hBf[40];
#pragma unroll
    for (int j = 0; j < 20; j++) {
        float lo, hi;
        up2(hA[j], lo, hi); hAf[2 * j] = lrelu(lo); hAf[2 * j + 1] = lrelu(hi);
        up2(hB[j], lo, hi); hBf[2 * j] = lrelu(lo); hBf[2 * j + 1] = lrelu(hi);
    }

    // out 40 -> 5 (scalar FFMA; odd fan-out, weights via uniform-const CSE)
    float xeA[5], xeB[5];
#pragma unroll
    for (int j = 0; j < 5; j++) {
        float aA = 0.f, aB = 0.f;
#pragma unroll
        for (int k = 0; k < 40; k++) {
            int idx = k * 5 + j;
            float lo, hi; up2(cWe2[idx >> 1], lo, hi);
            float w = (idx & 1) ? hi : lo;
            aA = fmaf(hAf[k], w, aA);
            aB = fmaf(hBf[k], w, aB);
        }
        xeA[j] = lrelu(aA);
        xeB[j] = lrelu(aB);
    }

    // store xe for both points: 10 consecutive floats, 8B-aligned -> 5 STG.64
    {
        float2* xo = (float2*)(g_xe + i0 * 5);
        xo[0] = make_float2(xeA[0], xeA[1]);
        xo[1] = make_float2(xeA[2], xeA[3]);
        xo[2] = make_float2(xeA[4], xeB[0]);
        xo[3] = make_float2(xeB[1], xeB[2]);
        xo[4] = make_float2(xeB[3], xeB[4]);
    }

    // segmented sum -> g_aggr
    int2 bb = *(const int2*)(batch + i0);
    int bA = bb.x, bB = bb.y;
    bool same = (bA == bB);
    unsigned peers = __match_any_sync(0xffffffffu, bA);
    int lane = tid & 31;
    int hiL = 31 - __clz(peers);
    bool leader = (lane == __ffs(peers) - 1);
#pragma unroll
    for (int c = 0; c < 5; c++) {
        float v = same ? (xeA[c] + xeB[c]) : xeA[c];
#pragma unroll
        for (int d = 1; d < 32; d <<= 1) {
            float s = __shfl_down_sync(0xffffffffu, v, d);
            if (lane + d <= hiL) v += s;
        }
        if (leader) atomicAdd(&g_aggr[bA * 5 + c], v);
        if (!same)  atomicAdd(&g_aggr[bB * 5 + c], xeB[c]);  // rare boundary leftover
    }
}

// =====================================================================
// Pass 2: x_global = ffn(x_aggr, Wg1[5x40], Wg2[40x4]); also zero g_pooled
// =====================================================================
__global__ void __launch_bounds__(256) k_glob() {
    int g = blockIdx.x * 256 + threadIdx.x;   // grid = NG/256 exactly

    // zero g_pooled: 128K float4 over 16384 threads -> 8 each
    {
        float4 z = make_float4(0.f, 0.f, 0.f, 0.f);
        float4* pp = (float4*)g_pooled;
#pragma unroll
        for (int r = 0; r < 8; r++) pp[g * 8 + r] = z;
    }

    float in5[5];
#pragma unroll
    for (int j = 0; j < 5; j++) in5[j] = g_aggr[g * 5 + j];

    u64 acc[20];
#pragma unroll
    for (int j = 0; j < 20; j++) acc[j] = 0ULL;
#pragma unroll
    for (int k = 0; k < 5; k++) {
        u64 a = pk2(in5[k], in5[k]);
#pragma unroll
        for (int q = 0; q < 20; q++) acc[q] = ffma2(a, cWg1[k * 20 + q], acc[q]);
    }
    float hf[40];
#pragma unroll
    for (int j = 0; j < 20; j++) {
        float lo, hi; up2(acc[j], lo, hi);
        hf[2 * j] = lrelu(lo); hf[2 * j + 1] = lrelu(hi);
    }
    // out 40 -> 4: output pairs (0,1) and (2,3) packed; weights [40][4] rows u64-aligned
    u64 o01 = 0ULL, o23 = 0ULL;
#pragma unroll
    for (int k = 0; k < 40; k++) {
        u64 a = pk2(hf[k], hf[k]);
        o01 = ffma2(a, cWg2[k * 2 + 0], o01);
        o23 = ffma2(a, cWg2[k * 2 + 1], o23);
    }
    float o0, o1, o2, o3;
    up2(o01, o0, o1); up2(o23, o2, o3);
    ((float4*)g_glob)[g] = make_float4(lrelu(o0), lrelu(o1), lrelu(o2), lrelu(o3));
}

// =====================================================================
// Pass 3: xo = ffn([xe, xg[batch]], Wo1[9x40], Wo2[40x32]); segment-sum -> g_pooled
// P=2 points/thread; layer2 in two 16-output halves (register cap).
// =====================================================================
__global__ void __launch_bounds__(256, 2) k_out(const int* __restrict__ batch) {
    int tid = threadIdx.x;
    int t = blockIdx.x * 256 + tid;
    int i0 = t * 2;
    if (i0 >= NPTS) return;

    int2 bb = *(const int2*)(batch + i0);
    int bA = bb.x, bB = bb.y;
    float4 xgA = ((const float4*)g_glob)[bA];
    float4 xgB = ((const float4*)g_glob)[bB];

    float inA[9], inB[9];
    {
        const float2* xep = (const float2*)(g_xe + i0 * 5);
        float2 e0 = xep[0], e1 = xep[1], e2 = xep[2], e3 = xep[3], e4 = xep[4];
        inA[0] = e0.x; inA[1] = e0.y; inA[2] = e1.x; inA[3] = e1.y; inA[4] = e2.x;
        inB[0] = e2.y; inB[1] = e3.x; inB[2] = e3.y; inB[3] = e4.x; inB[4] = e4.y;
        inA[5] = xgA.x; inA[6] = xgA.y; inA[7] = xgA.z; inA[8] = xgA.w;
        inB[5] = xgB.x; inB[6] = xgB.y; inB[7] = xgB.z; inB[8] = xgB.w;
    }

    // hidden 9 -> 40
    u64 hA[20], hB[20];
#pragma unroll
    for (int j = 0; j < 20; j++) { hA[j] = 0ULL; hB[j] = 0ULL; }
#pragma unroll
    for (int k = 0; k < 9; k++) {
        u64 aA = pk2(inA[k], inA[k]);
        u64 aB = pk2(inB[k], inB[k]);
#pragma unroll
        for (int q = 0; q < 20; q++) {
            u64 w = cWo1[k * 20 + q];
            hA[q] = ffma2(aA, w, hA[q]);
            hB[q] = ffma2(aB, w, hB[q]);
        }
    }
#pragma unroll
    for (int j = 0; j < 20; j++) {
        float lo, hi;
        up2(hA[j], lo, hi); hA[j] = pk2(lrelu(lo), lrelu(hi));
        up2(hB[j], lo, hi); hB[j] = pk2(lrelu(lo), lrelu(hi));
    }

    // segment bookkeeping (once)
    bool same = (bA == bB);
    unsigned peers = __match_any_sync(0xffffffffu, bA);
    int lane = tid & 31;
    int hiL = 31 - __clz(peers);
    bool leader = (lane == __ffs(peers) - 1);

    // out 40 -> 32, two halves of 16 outputs
#pragma unroll
    for (int hf = 0; hf < 2; hf++) {
        u64 oA[8], oB[8];
#pragma unroll
        for (int q = 0; q < 8; q++) { oA[q] = 0ULL; oB[q] = 0ULL; }
#pragma unroll
        for (int j = 0; j < 20; j++) {
            float a0, a1, b0, b1;
            up2(hA[j], a0, a1);
            up2(hB[j], b0, b1);
            {   // k = 2j: row base in u64s = (2j)*16, half offset hf*8
                u64 aA = pk2(a0, a0), aB = pk2(b0, b0);
#pragma unroll
                for (int q = 0; q < 8; q++) {
                    u64 w = cWo2[(2 * j) * 16 + hf * 8 + q];
                    oA[q] = ffma2(aA, w, oA[q]);
                    oB[q] = ffma2(aB, w, oB[q]);
                }
            }
            {   // k = 2j+1
                u64 aA = pk2(a1, a1), aB = pk2(b1, b1);
#pragma unroll
                for (int q = 0; q < 8; q++) {
                    u64 w = cWo2[(2 * j + 1) * 16 + hf * 8 + q];
                    oA[q] = ffma2(aA, w, oA[q]);
                    oB[q] = ffma2(aB, w, oB[q]);
                }
            }
        }
        // activation + pair-merge + warp segmented reduce + atomics
#pragma unroll
        for (int q = 0; q < 8; q++) {
            float lo, hi;
            up2(oA[q], lo, hi);
            float vA0 = lrelu(lo), vA1 = lrelu(hi);
            up2(oB[q], lo, hi);
            float vB0 = lrelu(lo), vB1 = lrelu(hi);
            int c = hf * 16 + 2 * q;
            float w0 = same ? (vA0 + vB0) : vA0;
            float w1 = same ? (vA1 + vB1) : vA1;
#pragma unroll
            for (int d = 1; d < 32; d <<= 1) {
                float s0 = __shfl_down_sync(0xffffffffu, w0, d);
                float s1 = __shfl_down_sync(0xffffffffu, w1, d);
                if (lane + d <= hiL) { w0 += s0; w1 += s1; }
            }
            if (leader) {
                atomicAdd(&g_pooled[bA * 32 + c],     w0);
                atomicAdd(&g_pooled[bA * 32 + c + 1], w1);
            }
            if (!same) {
                atomicAdd(&g_pooled[bB * 32 + c],     vB0);
                atomicAdd(&g_pooled[bB * 32 + c + 1], vB1);
            }
        }
    }
}

// =====================================================================
// Pass 4: out = ffn(pooled, Wd1[32x40], Wd2[40x1], final_linear=True)
// =====================================================================
__global__ void __launch_bounds__(256) k_disc(float* __restrict__ out) {
    int g = blockIdx.x * 256 + threadIdx.x;   // grid = NG/256 exactly
    float p[32];
#pragma unroll
    for (int j = 0; j < 32; j++) p[j] = g_pooled[g * 32 + j];

    u64 acc[20];
#pragma unroll
    for (int j = 0; j < 20; j++) acc[j] = 0ULL;
#pragma unroll
    for (int k = 0; k < 32; k++) {
        u64 a = pk2(p[k], p[k]);
#pragma unroll
        for (int q = 0; q < 20; q++) acc[q] = ffma2(a, cWd1[k * 20 + q], acc[q]);
    }
    u64 s = 0ULL;
#pragma unroll
    for (int j = 0; j < 20; j++) {
        float lo, hi; up2(acc[j], lo, hi);
        s = ffma2(pk2(lrelu(lo), lrelu(hi)), cWd2[j], s);
    }
    float lo, hi; up2(s, lo, hi);
    out[g] = lo + hi;   // final_linear: no activation
}

extern "C" void kernel_launch(void* const* d_in, const int* in_sizes, int n_in,
                              void* d_out, int out_size) {
    const float* x     = (const float*)d_in[0];
    const int*   batch = (const int*)d_in[1];
    float* out = (float*)d_out;

    // Stage weights into constant memory (async D2D: graph-capturable).
    cudaMemcpyToSymbolAsync(cWe1, d_in[2],  120 * 4, 0, cudaMemcpyDeviceToDevice, 0);
    cudaMemcpyToSymbolAsync(cWe2, d_in[3],  200 * 4, 0, cudaMemcpyDeviceToDevice, 0);
    cudaMemcpyToSymbolAsync(cWg1, d_in[4],  200 * 4, 0, cudaMemcpyDeviceToDevice, 0);
    cudaMemcpyToSymbolAsync(cWg2, d_in[5],  160 * 4, 0, cudaMemcpyDeviceToDevice, 0);
    cudaMemcpyToSymbolAsync(cWo1, d_in[6],  360 * 4, 0, cudaMemcpyDeviceToDevice, 0);
    cudaMemcpyToSymbolAsync(cWo2, d_in[7], 1280 * 4, 0, cudaMemcpyDeviceToDevice, 0);
    cudaMemcpyToSymbolAsync(cWd1, d_in[8], 1280 * 4, 0, cudaMemcpyDeviceToDevice, 0);
    cudaMemcpyToSymbolAsync(cWd2, d_in[9],   40 * 4, 0, cudaMemcpyDeviceToDevice, 0);

    const int nblk2 = (NPTS / 2 + 255) / 256;   // P=2 kernels
    k_zero<<<(NG * 5 / 4 + 255) / 256, 256>>>();
    k_emb<<<nblk2, 256>>>(x, batch);
    k_glob<<<NG / 256, 256>>>();
    k_out<<<nblk2, 256>>>(batch);
    k_disc<<<NG / 256, 256>>>(out);
}